// round 1
// baseline (speedup 1.0000x reference)
#include <cuda_runtime.h>
#include <cstddef>

// Linear recurrence scan: c_t = a_t * c_{t-1} + b_t   (c_{-1} = 0)
// input  : [B, T, 2*UNITS]  (a = [:, :, :UNITS], b = [:, :, UNITS:])
// output : [B, T, UNITS]
//
// One thread per (batch, unit) sequence. Adjacent threads process adjacent
// units -> fully coalesced 128B transactions on every load/store.
// Unroll-8 with explicit next-block prefetch to keep 16 LDGs in flight per
// warp while the dependent FMA chain drains the current block.

#ifndef UNITS_C
#define UNITS_C 2048
#endif
#ifndef T_C
#define T_C 2048
#endif

__global__ void __launch_bounds__(256, 1)
tempo_scan_kernel(const float* __restrict__ in, float* __restrict__ out)
{
    constexpr int UNITS = UNITS_C;
    constexpr int T     = T_C;
    constexpr int ROW   = 2 * UNITS;   // input row stride in elements
    constexpr int U     = 8;           // time unroll / prefetch depth

    const int tid = blockIdx.x * blockDim.x + threadIdx.x;
    const int g   = tid >> 11;         // batch index   (tid / UNITS)
    const int u   = tid & (UNITS - 1); // unit index

    const float* pa = in  + (size_t)g * T * ROW   + u;          // a[g, t, u]
    const float* pb = pa + UNITS;                                // b[g, t, u]
    float*       po = out + (size_t)g * T * UNITS + u;           // c[g, t, u]

    float a_cur[U], b_cur[U];

    // Prologue: prefetch block 0 (streaming loads; zero reuse, bypass-friendly)
    #pragma unroll
    for (int i = 0; i < U; ++i) {
        a_cur[i] = __ldcs(pa + (size_t)i * ROW);
        b_cur[i] = __ldcs(pb + (size_t)i * ROW);
    }

    float c = 0.0f;

    for (int t = 0; t < T; t += U) {
        float a_nxt[U], b_nxt[U];
        const int tn = t + U;
        if (tn < T) {
            // Prefetch the next time-block: 16 independent LDGs issued before
            // the dependent FMA chain of the current block.
            #pragma unroll
            for (int i = 0; i < U; ++i) {
                a_nxt[i] = __ldcs(pa + (size_t)(tn + i) * ROW);
                b_nxt[i] = __ldcs(pb + (size_t)(tn + i) * ROW);
            }
        }

        // Serial recurrence over the current block + streaming stores.
        #pragma unroll
        for (int i = 0; i < U; ++i) {
            c = fmaf(a_cur[i], c, b_cur[i]);
            __stcs(po + (size_t)(t + i) * UNITS, c);
        }

        #pragma unroll
        for (int i = 0; i < U; ++i) {
            a_cur[i] = a_nxt[i];
            b_cur[i] = b_nxt[i];
        }
    }
}

extern "C" void kernel_launch(void* const* d_in, const int* in_sizes, int n_in,
                              void* d_out, int out_size)
{
    const float* in  = (const float*)d_in[0];
    float*       out = (float*)d_out;

    // batch derived from input size: B * T * 2*UNITS elements
    const int batch  = in_sizes[0] / (T_C * 2 * UNITS_C);
    const int nthreads = batch * UNITS_C;          // one thread per sequence
    const int block = 256;
    const int grid  = (nthreads + block - 1) / block;   // 128 for B=16

    tempo_scan_kernel<<<grid, block>>>(in, out);
}